// round 10
// baseline (speedup 1.0000x reference)
#include <cuda_runtime.h>
#include <float.h>
#include <math.h>
#include <cstdint>

// x = [B=16, C=2048, H=48, W=64] fp32. 21 regions; 6 row ranges from 6 row
// segments (breakpoints 0,12,16,24,32,36,48).
#define B_  16
#define C_  2048
#define H_  48
#define W_  64
#define NPLANE (B_ * C_)
#define R_  21
#define EPS_ 1e-6f

#define SLAB_BYTES (R_ * C_ * 4)              // 172032 bytes per batch

// vecs layout: [b][c][r]  (element (b,c,r) at (b*C + c)*R + r)
__device__ float g_vecs[B_ * C_ * R_];

// RR0=[0,48) RR1=[0,32) RR2=[16,48) RR3=[0,24) RR4=[12,36) RR5=[24,48)
__constant__ int REG_RR[R_] = {
    0,
    0, 0,
    1, 1, 1,
    2, 2, 2,
    3, 3, 3, 3,
    4, 4, 4, 4,
    5, 5, 5, 5
};
__constant__ int REG_C0[R_] = {
    0,
    0, 16,
    0, 16, 32,
    0, 16, 32,
    0, 13, 26, 40,
    0, 13, 26, 40,
    0, 13, 26, 40
};
__constant__ int REG_C1[R_] = {
    64,
    48, 64,
    32, 48, 64,
    32, 48, 64,
    24, 37, 50, 64,
    24, 37, 50, 64,
    24, 37, 50, 64
};

__device__ __forceinline__ uint32_t smem_u32(const void* p) {
    return (uint32_t)__cvta_generic_to_shared(p);
}

__device__ __forceinline__ void mbar_wait_parity0(uint32_t mbar) {
    asm volatile(
        "{\n\t"
        ".reg .pred P;\n\t"
        "WAIT_%=:\n\t"
        "mbarrier.try_wait.parity.acquire.cta.shared::cta.b64 P, [%0], 0, 0x989680;\n\t"
        "@P bra DONE_%=;\n\t"
        "bra WAIT_%=;\n\t"
        "DONE_%=:\n\t"
        "}"
        :: "r"(mbar) : "memory");
}

// ---------------------------------------------------------------------------
// Kernel 1 (frozen load path, 70.7us / DRAM 73%): one block per (b,c) plane,
// 64 threads = one per column. Scalar coalesced LDG.32 column-walk, 6 segment
// maxes in registers, 6 row-range maxes in smem, 21 region reductions.
// CHANGED: stores go to vecs[plane*21+reg] -> 21 results per plane land in 3
// DRAM sectors instead of 21 (write traffic 22MB -> 3MB).
// ---------------------------------------------------------------------------
__global__ __launch_bounds__(64) void rpool_max_kernel(
    const float* __restrict__ x, float* __restrict__ vecs)
{
    const int plane = blockIdx.x;             // b * C + c
    const float* __restrict__ p = x + (size_t)plane * (H_ * W_);
    const int col = threadIdx.x;              // 0..63

    float s0 = -FLT_MAX, s1 = -FLT_MAX, s2 = -FLT_MAX;
    float s3 = -FLT_MAX, s4 = -FLT_MAX, s5 = -FLT_MAX;

    #pragma unroll
    for (int r = 0; r < 12; r++)  s0 = fmaxf(s0, p[r * W_ + col]);
    #pragma unroll
    for (int r = 12; r < 16; r++) s1 = fmaxf(s1, p[r * W_ + col]);
    #pragma unroll
    for (int r = 16; r < 24; r++) s2 = fmaxf(s2, p[r * W_ + col]);
    #pragma unroll
    for (int r = 24; r < 32; r++) s3 = fmaxf(s3, p[r * W_ + col]);
    #pragma unroll
    for (int r = 32; r < 36; r++) s4 = fmaxf(s4, p[r * W_ + col]);
    #pragma unroll
    for (int r = 36; r < 48; r++) s5 = fmaxf(s5, p[r * W_ + col]);

    __shared__ float rr[6][W_];
    const float m012 = fmaxf(fmaxf(s0, s1), s2);
    const float m345 = fmaxf(fmaxf(s3, s4), s5);
    rr[0][col] = fmaxf(m012, m345);                     // rows [0,48)
    rr[1][col] = fmaxf(m012, s3);                       // rows [0,32)
    rr[2][col] = fmaxf(fmaxf(s2, s3), fmaxf(s4, s5));   // rows [16,48)
    rr[3][col] = m012;                                  // rows [0,24)
    rr[4][col] = fmaxf(fmaxf(s1, s2), fmaxf(s3, s4));   // rows [12,36)
    rr[5][col] = m345;                                  // rows [24,48)
    __syncthreads();

    const int warp = threadIdx.x >> 5;
    const int lane = threadIdx.x & 31;

    for (int reg = warp; reg < R_; reg += 2) {
        const int ri = REG_RR[reg];
        const int c0 = REG_C0[reg];
        const int c1 = REG_C1[reg];
        float m = -FLT_MAX;
        for (int cc = c0 + lane; cc < c1; cc += 32)
            m = fmaxf(m, rr[ri][cc]);
        #pragma unroll
        for (int o = 16; o > 0; o >>= 1)
            m = fmaxf(m, __shfl_xor_sync(0xffffffffu, m, o));
        if (lane == 0)
            vecs[(size_t)plane * R_ + reg] = m;    // [b][c][r] layout
    }
}

// ---------------------------------------------------------------------------
// Kernel 2 (backend): 16 blocks x 1024 threads, 168KB dynamic smem.
// The batch slab is pulled in with ONE cp.async.bulk (DMA engine: no
// register-MLP limit on the DRAM stream). All compute then runs from smem:
//   pass 1: warps 0-20 each reduce one region's sum of squares (stride-21
//           scalar LDS, conflict-free) -> inv[r].
//   pass 2: all 1024 threads aggregate 2 channels each, block-reduce the
//           global norm, scale, coalesced scalar stores.
// ---------------------------------------------------------------------------
__global__ __launch_bounds__(1024) void rpool_normagg_kernel(
    const float* __restrict__ vecs, float* __restrict__ out)
{
    extern __shared__ float slab[];            // [C_][R_] floats
    __shared__ __align__(8) unsigned long long mbar;
    __shared__ float inv[R_];
    __shared__ float ws[32];
    __shared__ float s_invn;

    const int b = blockIdx.x;
    const int tid = threadIdx.x;
    const int warp = tid >> 5;                 // 0..31
    const int lane = tid & 31;

    const uint32_t mbar_a = smem_u32(&mbar);
    if (tid == 0) {
        asm volatile("mbarrier.init.shared.b64 [%0], 1;" :: "r"(mbar_a));
    }
    __syncthreads();
    if (tid == 0) {
        asm volatile(
            "mbarrier.arrive.expect_tx.shared.b64 _, [%0], %1;"
            :: "r"(mbar_a), "r"((uint32_t)SLAB_BYTES) : "memory");
        const uint32_t dst = smem_u32(slab);
        const float* src = vecs + (size_t)b * (R_ * C_);
        asm volatile(
            "cp.async.bulk.shared::cluster.global.mbarrier::complete_tx::bytes "
            "[%0], [%1], %2, [%3];"
            :: "r"(dst), "l"(src), "r"((uint32_t)SLAB_BYTES), "r"(mbar_a)
            : "memory");
    }
    mbar_wait_parity0(mbar_a);

    // ---- pass 1: warp-per-region sum of squares from smem ----
    if (warp < R_) {
        const int r = warp;
        float acc = 0.f;
        #pragma unroll
        for (int k = 0; k < 64; k++) {
            const float v = slab[(lane + k * 32) * R_ + r];
            acc += v * v;
        }
        #pragma unroll
        for (int o = 16; o > 0; o >>= 1)
            acc += __shfl_xor_sync(0xffffffffu, acc, o);
        if (lane == 0)
            inv[r] = 1.0f / (sqrtf(acc) + EPS_);
    }
    __syncthreads();

    // ---- pass 2: aggregate 2 channels/thread + global L2 normalize ----
    float sA = 0.f, sB = 0.f;
    {
        const float* rowA = slab + (size_t)tid * R_;
        const float* rowB = slab + (size_t)(tid + 1024) * R_;
        #pragma unroll
        for (int r = 0; r < R_; r++) {
            sA += rowA[r] * inv[r];
            sB += rowB[r] * inv[r];
        }
    }
    float local = sA * sA + sB * sB;

    #pragma unroll
    for (int o = 16; o > 0; o >>= 1)
        local += __shfl_xor_sync(0xffffffffu, local, o);
    if (lane == 0) ws[warp] = local;
    __syncthreads();
    if (warp == 0) {
        float t = ws[lane];
        #pragma unroll
        for (int o = 16; o > 0; o >>= 1)
            t += __shfl_xor_sync(0xffffffffu, t, o);
        if (lane == 0) s_invn = 1.0f / (sqrtf(t) + EPS_);
    }
    __syncthreads();

    const float invn = s_invn;
    out[(size_t)b * C_ + tid]        = sA * invn;
    out[(size_t)b * C_ + tid + 1024] = sB * invn;
}

extern "C" void kernel_launch(void* const* d_in, const int* in_sizes, int n_in,
                              void* d_out, int out_size)
{
    const float* x = (const float*)d_in[0];
    float* out = (float*)d_out;

    float* vecs;
    cudaGetSymbolAddress((void**)&vecs, g_vecs);

    static int smem_set = 0;
    if (!smem_set) {
        cudaFuncSetAttribute(rpool_normagg_kernel,
                             cudaFuncAttributeMaxDynamicSharedMemorySize,
                             SLAB_BYTES);
        smem_set = 1;
    }

    rpool_max_kernel<<<NPLANE, 64>>>(x, vecs);
    rpool_normagg_kernel<<<B_, 1024, SLAB_BYTES>>>(vecs, out);
}